// round 13
// baseline (speedup 1.0000x reference)
#include <cuda_runtime.h>
#include <math.h>

#define NB 2
#define NF 4096
#define NQ 16384
#define NPTS (NB*NQ)                  // 32768
#define BLOCK 128
#define PTS_PER_THREAD 4
#define SPLITS 16
#define TRIS_PER_SPLIT (NF/SPLITS)    // 256
#define PAIRS_PER_SPLIT (TRIS_PER_SPLIT/2)  // 128 -> single 20KB smem tile

typedef unsigned long long u64;

// Scratch (static __device__ arrays: allowed; no allocs anywhere)
__device__ float4 g_tc2[NB*(NF/2)*10];   // pair-interleaved consts: 10 x float4 per tri-pair
__device__ uint2  g_cand[NPTS*SPLITS];   // per (point,split): top-2 triangle indices

// ---- f32x2 packed helpers (sm_100a; add/mul/fma only) ----
__device__ __forceinline__ u64 f2pack(float lo, float hi) {
    u64 r; asm("mov.b64 %0, {%1, %2};" : "=l"(r) : "f"(lo), "f"(hi)); return r;
}
__device__ __forceinline__ void f2unpack(u64 v, float& lo, float& hi) {
    asm("mov.b64 {%0, %1}, %2;" : "=f"(lo), "=f"(hi) : "l"(v));
}
__device__ __forceinline__ u64 f2add(u64 a, u64 b) {
    u64 r; asm("add.rn.f32x2 %0, %1, %2;" : "=l"(r) : "l"(a), "l"(b)); return r;
}
__device__ __forceinline__ u64 f2mul(u64 a, u64 b) {
    u64 r; asm("mul.rn.f32x2 %0, %1, %2;" : "=l"(r) : "l"(a), "l"(b)); return r;
}
__device__ __forceinline__ u64 f2fma(u64 a, u64 b, u64 c) {
    u64 r; asm("fma.rn.f32x2 %0, %1, %2, %3;" : "=l"(r) : "l"(a), "l"(b), "l"(c)); return r;
}
// scalar multiply with saturate-to-[0,1] folded in
__device__ __forceinline__ float fmul_sat(float a, float b) {
    float r; asm("mul.rn.sat.f32 %0, %1, %2;" : "=f"(r) : "f"(a), "f"(b)); return r;
}

__device__ __forceinline__ float guard_inv(float x) {
    return (fabsf(x) > 1e-12f) ? (1.0f / x) : 1.0f;
}
__device__ __forceinline__ double dclamp01(double x) {
    return fmin(fmax(x, 0.0), 1.0);
}
__device__ __forceinline__ double dsafe_div(double num, double den) {
    double d = (fabs(den) > 1e-12) ? den : 1.0;
    return num / d;
}

// ---------------------------------------------------------------------------
// Kernel 0: per-triangle constants, pair-interleaved, POSITIVE reciprocals
// (R11/R12 layout, proven).
// ---------------------------------------------------------------------------
__global__ void k_pre(const float* __restrict__ tris) {
    int i = blockIdx.x * blockDim.x + threadIdx.x;
    if (i >= NB * NF) return;
    const float* t = tris + (size_t)i * 9;
    float ax = t[0], ay = t[1], az = t[2];
    float bx = t[3], by = t[4], bz = t[5];
    float cx = t[6], cy = t[7], cz = t[8];
    float abx = bx - ax, aby = by - ay, abz = bz - az;
    float acx = cx - ax, acy = cy - ay, acz = cz - az;
    float aa = abx*abx + aby*aby + abz*abz;
    float bb = acx*acx + acy*acy + acz*acz;
    float gg = abx*acx + aby*acy + abz*acz;
    float cb2 = aa + bb - 2.0f*gg;
    float den = aa*bb - gg*gg;

    int pi = i >> 1, lane = i & 1;
    float* o = ((float*)g_tc2) + (size_t)pi * 40 + lane;
    o[ 0] = -ax;  o[ 2] = -ay;  o[ 4] = -az;
    o[ 6] = abx;  o[ 8] = aby;  o[10] = abz;
    o[12] = acx;  o[14] = acy;  o[16] = acz;
    o[18] = aa;   o[20] = bb;   o[22] = -gg;
    o[24] = guard_inv(aa);  o[26] = guard_inv(bb);
    o[28] = guard_inv(cb2); o[30] = guard_inv(den);
    o[32] = aa - gg; o[34] = cb2; o[36] = den; o[38] = 0.0f;
}

// per-lane edge/interior selection -> POSITIVE (v,w).
// Selection distances are APP-relative (common term cancelled; selection-only
// noise, absorbed by top-2 + f64 arbitration as established in R6).
__device__ __forceinline__ void lane_sel(
    float vb, float vc, float vbc, float den,
    float qab, float qac, float qbc,
    float ta, float tb, float tc,
    float vi, float wi, float& v, float& w)
{
    bool inside = (vb >= 0.0f) && (vc >= 0.0f) && (vbc <= den);
    bool pab = qab <= qac;
    float ve = pab ? ta : 0.0f;
    float we = pab ? 0.0f : tb;
    float de = fminf(qab, qac);
    bool pbc = de <= qbc;
    float vbcv = 1.0f - tc;
    ve = pbc ? ve : vbcv;
    we = pbc ? we : tc;
    v = inside ? vi : ve;
    w = inside ? wi : we;
}

// insert the sorted lane pair (dmin first, dmax only contests best2)
__device__ __forceinline__ void top2_ins2(
    float dist0, float dist1, int te,
    float& best, int& bidx, float& best2, int& bidx2)
{
    float dmin = fminf(dist0, dist1);
    float dmax = fmaxf(dist0, dist1);
    bool first = dist0 <= dist1;
    int imin = first ? te : te + 1;
    int imax = first ? te + 1 : te;

    bool lt1 = dmin < best;
    bool lt2 = dmin < best2;
    best2 = lt1 ? best : (lt2 ? dmin : best2);
    bidx2 = lt1 ? bidx : (lt2 ? imin : bidx2);
    best  = lt1 ? dmin : best;
    bidx  = lt1 ? imin : bidx;

    bool l3 = dmax < best2;
    best2 = l3 ? dmax : best2;
    bidx2 = l3 ? imax : bidx2;
}

// Evaluate one packed triangle-pair against one point (R11 sat-clamp body,
// APP-free selection; emitted DIST pipeline bitwise == proven R7/R11).
__device__ __forceinline__ void eval_pair(
    u64 PX, u64 PY, u64 PZ, u64 KN1,
    u64 NAX, u64 NAY, u64 NAZ, u64 ABX, u64 ABY, u64 ABZ,
    u64 ACX, u64 ACY, u64 ACZ, u64 AA, u64 BB, u64 NGG,
    u64 IA, u64 IB, u64 IC, u64 ID, u64 AMG, u64 CB2, u64 DEN,
    int te, float& best, int& bidx, float& best2, int& bidx2)
{
    u64 APX = f2add(PX, NAX);
    u64 APY = f2add(PY, NAY);
    u64 APZ = f2add(PZ, NAZ);

    u64 D1  = f2fma(ABX, APX, f2fma(ABY, APY, f2mul(ABZ, APZ)));
    u64 D2  = f2fma(ACX, APX, f2fma(ACY, APY, f2mul(ACZ, APZ)));

    u64 VC  = f2fma(AA, D2, f2mul(NGG, D1));
    u64 VB  = f2fma(BB, D1, f2mul(NGG, D2));
    u64 VBC = f2add(VB, VC);

    u64 E1 = f2add(f2fma(KN1, D1, D2), AMG);

    float d1l0, d1l1, d2l0, d2l1, e1l0, e1l1;
    f2unpack(D1, d1l0, d1l1);
    f2unpack(D2, d2l0, d2l1);
    f2unpack(E1, e1l0, e1l1);
    float ia0, ia1, ib0, ib1, ic0, ic1;
    f2unpack(IA, ia0, ia1);
    f2unpack(IB, ib0, ib1);
    f2unpack(IC, ic0, ic1);
    float ta0 = fmul_sat(d1l0, ia0), ta1 = fmul_sat(d1l1, ia1);
    float tb0 = fmul_sat(d2l0, ib0), tb1 = fmul_sat(d2l1, ib1);
    float tc0 = fmul_sat(e1l0, ic0), tc1 = fmul_sat(e1l1, ic1);
    u64 TA = f2pack(ta0, ta1);
    u64 TB = f2pack(tb0, tb1);
    u64 TC = f2pack(tc0, tc1);

    // APP-relative selection distances (common +APP term cancelled)
    u64 D1_2  = f2add(D1, D1);
    u64 ND1_2 = f2mul(D1_2, KN1);
    u64 QAB = f2mul(TA, f2fma(TA, AA, ND1_2));
    u64 ND2_2 = f2mul(f2add(D2, D2), KN1);
    u64 QAC = f2mul(TB, f2fma(TB, BB, ND2_2));
    u64 AMD2 = f2add(AA, ND1_2);                   // aa - 2*d1
    u64 NE1_2 = f2mul(f2add(E1, E1), KN1);
    u64 QBC = f2fma(TC, f2fma(TC, CB2, NE1_2), AMD2);

    u64 VI = f2mul(VB, ID);
    u64 WI = f2mul(VC, ID);

    float vb0, vb1, vc0, vc1, vbc0, vbc1, den0, den1;
    float qab0, qab1, qac0, qac1, qbc0, qbc1, vi0, vi1, wi0, wi1;
    f2unpack(VB, vb0, vb1);    f2unpack(VC, vc0, vc1);
    f2unpack(VBC, vbc0, vbc1); f2unpack(DEN, den0, den1);
    f2unpack(QAB, qab0, qab1); f2unpack(QAC, qac0, qac1);
    f2unpack(QBC, qbc0, qbc1);
    f2unpack(VI, vi0, vi1);    f2unpack(WI, wi0, wi1);

    float v0, w0, v1, w1;
    lane_sel(vb0, vc0, vbc0, den0, qab0, qac0, qbc0, ta0, tb0, tc0, vi0, wi0, v0, w0);
    lane_sel(vb1, vc1, vbc1, den1, qab1, qac1, qbc1, ta1, tb1, tc1, vi1, wi1, v1, w1);

    u64 NV = f2mul(f2pack(v0, v1), KN1);
    u64 NW = f2mul(f2pack(w0, w1), KN1);

    u64 DX = f2fma(NV, ABX, f2fma(NW, ACX, APX));
    u64 DY = f2fma(NV, ABY, f2fma(NW, ACY, APY));
    u64 DZ = f2fma(NV, ABZ, f2fma(NW, ACZ, APZ));
    u64 DIST = f2fma(DX, DX, f2fma(DY, DY, f2mul(DZ, DZ)));
    float dist0, dist1;
    f2unpack(DIST, dist0, dist1);

    top2_ins2(dist0, dist1, te, best, bidx, best2, bidx2);
}

// ---------------------------------------------------------------------------
// Kernel 1: brute-force scan; 4 points per thread share each loaded triangle
// pair (amortized LDS + ILP). Single smem tile per split (128 pairs, 20KB).
// Top-2 per (point, split); f64 arbitration downstream.
// ---------------------------------------------------------------------------
__global__ void __launch_bounds__(BLOCK, 4) k_main(const float* __restrict__ points) {
    __shared__ ulonglong2 sh[PAIRS_PER_SPLIT * 10];
    int b = blockIdx.z;
    int qBase = blockIdx.x * (BLOCK * PTS_PER_THREAD) + threadIdx.x;
    const u64 KN1 = f2pack(-1.0f, -1.0f);
    int pairBase = blockIdx.y * PAIRS_PER_SPLIT;

    u64 PX[PTS_PER_THREAD], PY[PTS_PER_THREAD], PZ[PTS_PER_THREAD];
    float best[PTS_PER_THREAD], best2[PTS_PER_THREAD];
    int bidx[PTS_PER_THREAD], bidx2[PTS_PER_THREAD];
    #pragma unroll
    for (int p = 0; p < PTS_PER_THREAD; p++) {
        const float* pp = points + (size_t)(b * NQ + qBase + p * BLOCK) * 3;
        PX[p] = f2pack(pp[0], pp[0]);
        PY[p] = f2pack(pp[1], pp[1]);
        PZ[p] = f2pack(pp[2], pp[2]);
        best[p] = 3.402823e38f;  bidx[p] = pairBase * 2;
        best2[p] = 3.402823e38f; bidx2[p] = pairBase * 2;
    }

    {
        const float4* src = g_tc2 + (size_t)(b * (NF/2) + pairBase) * 10;
        float4* dst = (float4*)sh;
        for (int i = threadIdx.x; i < PAIRS_PER_SPLIT * 10; i += BLOCK) dst[i] = src[i];
    }
    __syncthreads();

    #pragma unroll 2
    for (int j = 0; j < PAIRS_PER_SPLIT; j++) {
        const ulonglong2* tp = sh + j * 10;
        ulonglong2 s0 = tp[0], s1 = tp[1], s2 = tp[2], s3 = tp[3], s4 = tp[4];
        ulonglong2 s5 = tp[5], s6 = tp[6], s7 = tp[7], s8 = tp[8], s9 = tp[9];
        u64 NAX = s0.x, NAY = s0.y, NAZ = s1.x, ABX = s1.y;
        u64 ABY = s2.x, ABZ = s2.y, ACX = s3.x, ACY = s3.y;
        u64 ACZ = s4.x, AA  = s4.y, BB  = s5.x, NGG = s5.y;
        u64 IA  = s6.x, IB  = s6.y, IC  = s7.x, ID  = s7.y;
        u64 AMG = s8.x, CB2 = s8.y, DEN = s9.x;

        int te = (pairBase + j) * 2;
        #pragma unroll
        for (int p = 0; p < PTS_PER_THREAD; p++) {
            eval_pair(PX[p], PY[p], PZ[p], KN1,
                      NAX, NAY, NAZ, ABX, ABY, ABZ, ACX, ACY, ACZ, AA, BB, NGG,
                      IA, IB, IC, ID, AMG, CB2, DEN,
                      te, best[p], bidx[p], best2[p], bidx2[p]);
        }
    }

    #pragma unroll
    for (int p = 0; p < PTS_PER_THREAD; p++) {
        g_cand[(size_t)(b * NQ + qBase + p * BLOCK) * SPLITS + blockIdx.y] =
            make_uint2((unsigned)bidx[p], (unsigned)bidx2[p]);
    }
}

// ---------------------------------------------------------------------------
// Reference formula in DOUBLE precision (true-math ordering for arbitration).
// ---------------------------------------------------------------------------
__device__ void ref_eval_d(const float* __restrict__ tp,
                           double px, double py, double pz,
                           double& d2out, double& rxo, double& ryo, double& rzo) {
    double ax = tp[0], ay = tp[1], az = tp[2];
    double bx = tp[3], by = tp[4], bz = tp[5];
    double cx = tp[6], cy = tp[7], cz = tp[8];

    double abx = bx - ax, aby = by - ay, abz = bz - az;
    double acx = cx - ax, acy = cy - ay, acz = cz - az;
    double apx = px - ax, apy = py - ay, apz = pz - az;
    double d1 = abx*apx + aby*apy + abz*apz;
    double d2 = acx*apx + acy*apy + acz*apz;
    double bpx = px - bx, bpy = py - by, bpz = pz - bz;
    double d3 = abx*bpx + aby*bpy + abz*bpz;
    double d4 = acx*bpx + acy*bpy + acz*bpz;
    double cpx = px - cx, cpy = py - cy, cpz = pz - cz;
    double d5 = abx*cpx + aby*cpy + abz*cpz;
    double d6 = acx*cpx + acy*cpy + acz*cpz;

    double vc = d1*d4 - d3*d2;
    double vb = d5*d2 - d1*d6;
    double va = d3*d6 - d5*d4;
    double v_ab = dclamp01(dsafe_div(d1, d1 - d3));
    double w_ac = dclamp01(dsafe_div(d2, d2 - d6));
    double w_bc = dclamp01(dsafe_div(d4 - d3, (d4 - d3) + (d5 - d6)));
    double denom = va + vb + vc;
    double v = dsafe_div(vb, denom);
    double w = dsafe_div(vc, denom);

    double rx = ax + abx*v + acx*w;
    double ry = ay + aby*v + acy*w;
    double rz = az + abz*v + acz*w;

    bool m_bc = (va <= 0.0) && ((d4 - d3) >= 0.0) && ((d5 - d6) >= 0.0);
    if (m_bc) { rx = bx + w_bc*(cx - bx); ry = by + w_bc*(cy - by); rz = bz + w_bc*(cz - bz); }
    bool m_ac = (vb <= 0.0) && (d2 >= 0.0) && (d6 <= 0.0);
    if (m_ac) { rx = ax + w_ac*acx; ry = ay + w_ac*acy; rz = az + w_ac*acz; }
    bool m_ab = (vc <= 0.0) && (d1 >= 0.0) && (d3 <= 0.0);
    if (m_ab) { rx = ax + v_ab*abx; ry = ay + v_ab*aby; rz = az + v_ab*abz; }
    bool m_c = (d6 >= 0.0) && (d5 <= d6);
    if (m_c) { rx = cx; ry = cy; rz = cz; }
    bool m_b = (d3 >= 0.0) && (d4 <= d3);
    if (m_b) { rx = bx; ry = by; rz = bz; }
    bool m_a = (d1 <= 0.0) && (d2 <= 0.0);
    if (m_a) { rx = ax; ry = ay; rz = az; }

    double dxx = px - rx, dyy = py - ry, dzz = pz - rz;
    d2out = dxx*dxx + dyy*dyy + dzz*dzz;
    rxo = rx; ryo = ry; rzo = rz;
}

// ---------------------------------------------------------------------------
// Kernel 2: PARALLEL arbitration — 8 threads per point, each f64-evaluates 4
// of the 32 candidates; butterfly-reduce (bestD, bestI) with idx tie-break;
// sub-lane 0 recomputes the winner's closest point and writes outputs.
// ---------------------------------------------------------------------------
__global__ void k_fin(const float* __restrict__ tris,
                      const float* __restrict__ points,
                      float* __restrict__ out) {
    int gid = blockIdx.x * blockDim.x + threadIdx.x;
    int i = gid >> 3;         // point index
    int sub = gid & 7;        // eighth (splits 2*sub, 2*sub+1)
    if (i >= NPTS) return;
    int b = i / NQ;

    const float* pp = points + (size_t)i * 3;
    double px = pp[0], py = pp[1], pz = pp[2];

    double bestD = 1e300;
    int bestI = 0x7FFFFFFF;

    #pragma unroll
    for (int s = sub * 2; s < sub * 2 + 2; s++) {
        uint2 c = g_cand[(size_t)i * SPLITS + s];
        #pragma unroll
        for (int k = 0; k < 2; k++) {
            int idx = (k == 0) ? (int)c.x : (int)c.y;
            const float* tp = tris + (size_t)(b * NF + idx) * 9;
            double d2, rx, ry, rz;
            ref_eval_d(tp, px, py, pz, d2, rx, ry, rz);
            bool take = (d2 < bestD) || (d2 == bestD && idx < bestI);
            if (take) { bestD = d2; bestI = idx; }
        }
    }

    // butterfly reduce over the 8 sub-lanes (same warp: gid consecutive)
    #pragma unroll
    for (int off = 1; off < 8; off <<= 1) {
        double oD = __shfl_xor_sync(0xFFFFFFFFu, bestD, off);
        int    oI = __shfl_xor_sync(0xFFFFFFFFu, bestI, off);
        if (oD < bestD || (oD == bestD && oI < bestI)) { bestD = oD; bestI = oI; }
    }

    if (sub == 0) {
        const float* tp = tris + (size_t)(b * NF + bestI) * 9;
        double d2, rx, ry, rz;
        ref_eval_d(tp, px, py, pz, d2, rx, ry, rz);
        out[i] = (float)d2;                                  // distances [2,16384]
        out[NPTS + (size_t)i*3 + 0] = (float)rx;             // closest_points
        out[NPTS + (size_t)i*3 + 1] = (float)ry;
        out[NPTS + (size_t)i*3 + 2] = (float)rz;
        out[(size_t)NPTS*4 + i] = (float)bestI;              // closest_faces
    }
}

extern "C" void kernel_launch(void* const* d_in, const int* in_sizes, int n_in,
                              void* d_out, int out_size) {
    const float* tris = (const float*)d_in[0];   // [2,4096,3,3]
    const float* pts  = (const float*)d_in[1];   // [2,16384,3]
    float* out = (float*)d_out;

    k_pre<<<(NB*NF + 255) / 256, 256>>>(tris);
    dim3 grid(NQ / (BLOCK * PTS_PER_THREAD), SPLITS, NB);
    k_main<<<grid, BLOCK>>>(pts);
    k_fin<<<(NPTS * 8 + 255) / 256, 256>>>(tris, pts, out);
}

// round 14
// speedup vs baseline: 1.0556x; 1.0556x over previous
#include <cuda_runtime.h>
#include <math.h>

#define NB 2
#define NF 4096
#define NQ 16384
#define NPTS (NB*NQ)                  // 32768
#define BLOCK 128
#define PTS_PER_THREAD 2
#define SPLITS 8
#define TRIS_PER_SPLIT (NF/SPLITS)    // 512
#define PAIRS_PER_SPLIT (TRIS_PER_SPLIT/2)  // 256
#define TILE_PAIRS 128                // 256 triangles per smem tile, 20KB

typedef unsigned long long u64;

// Scratch (static __device__ arrays: allowed; no allocs anywhere)
__device__ float4 g_tc2[NB*(NF/2)*10];   // pair-interleaved consts: 10 x float4 per tri-pair
__device__ uint2  g_cand[NPTS*SPLITS];   // per (point,split): top-2 triangle indices

// ---- f32x2 packed helpers (sm_100a; add/mul/fma only) ----
__device__ __forceinline__ u64 f2pack(float lo, float hi) {
    u64 r; asm("mov.b64 %0, {%1, %2};" : "=l"(r) : "f"(lo), "f"(hi)); return r;
}
__device__ __forceinline__ void f2unpack(u64 v, float& lo, float& hi) {
    asm("mov.b64 {%0, %1}, %2;" : "=f"(lo), "=f"(hi) : "l"(v));
}
__device__ __forceinline__ u64 f2add(u64 a, u64 b) {
    u64 r; asm("add.rn.f32x2 %0, %1, %2;" : "=l"(r) : "l"(a), "l"(b)); return r;
}
__device__ __forceinline__ u64 f2mul(u64 a, u64 b) {
    u64 r; asm("mul.rn.f32x2 %0, %1, %2;" : "=l"(r) : "l"(a), "l"(b)); return r;
}
__device__ __forceinline__ u64 f2fma(u64 a, u64 b, u64 c) {
    u64 r; asm("fma.rn.f32x2 %0, %1, %2, %3;" : "=l"(r) : "l"(a), "l"(b), "l"(c)); return r;
}
// scalar multiply with saturate-to-[0,1] folded in
__device__ __forceinline__ float fmul_sat(float a, float b) {
    float r; asm("mul.rn.sat.f32 %0, %1, %2;" : "=f"(r) : "f"(a), "f"(b)); return r;
}

__device__ __forceinline__ float guard_inv(float x) {
    return (fabsf(x) > 1e-12f) ? (1.0f / x) : 1.0f;
}
__device__ __forceinline__ double dclamp01(double x) {
    return fmin(fmax(x, 0.0), 1.0);
}
__device__ __forceinline__ double dsafe_div(double num, double den) {
    double d = (fabs(den) > 1e-12) ? den : 1.0;
    return num / d;
}

// ---------------------------------------------------------------------------
// Kernel 0: per-triangle constants, pair-interleaved, POSITIVE reciprocals
// (R11/R12 layout, proven).
// ---------------------------------------------------------------------------
__global__ void k_pre(const float* __restrict__ tris) {
    int i = blockIdx.x * blockDim.x + threadIdx.x;
    if (i >= NB * NF) return;
    const float* t = tris + (size_t)i * 9;
    float ax = t[0], ay = t[1], az = t[2];
    float bx = t[3], by = t[4], bz = t[5];
    float cx = t[6], cy = t[7], cz = t[8];
    float abx = bx - ax, aby = by - ay, abz = bz - az;
    float acx = cx - ax, acy = cy - ay, acz = cz - az;
    float aa = abx*abx + aby*aby + abz*abz;
    float bb = acx*acx + acy*acy + acz*acz;
    float gg = abx*acx + aby*acy + abz*acz;
    float cb2 = aa + bb - 2.0f*gg;
    float den = aa*bb - gg*gg;

    int pi = i >> 1, lane = i & 1;
    float* o = ((float*)g_tc2) + (size_t)pi * 40 + lane;
    o[ 0] = -ax;  o[ 2] = -ay;  o[ 4] = -az;
    o[ 6] = abx;  o[ 8] = aby;  o[10] = abz;
    o[12] = acx;  o[14] = acy;  o[16] = acz;
    o[18] = aa;   o[20] = bb;   o[22] = -gg;
    o[24] = guard_inv(aa);  o[26] = guard_inv(bb);
    o[28] = guard_inv(cb2); o[30] = guard_inv(den);
    o[32] = aa - gg; o[34] = cb2; o[36] = den; o[38] = 0.0f;
}

// per-lane edge/interior selection -> POSITIVE (v,w).
// Selection distances are APP-relative (common +APP cancelled; selection-only
// noise, absorbed by top-2 + f64 arbitration per R6 precedent).
__device__ __forceinline__ void lane_sel(
    float vb, float vc, float vbc, float den,
    float qab, float qac, float qbc,
    float ta, float tb, float tc,
    float vi, float wi, float& v, float& w)
{
    bool inside = (vb >= 0.0f) && (vc >= 0.0f) && (vbc <= den);
    bool pab = qab <= qac;
    float ve = pab ? ta : 0.0f;
    float we = pab ? 0.0f : tb;
    float de = fminf(qab, qac);
    bool pbc = de <= qbc;
    float vbcv = 1.0f - tc;
    ve = pbc ? ve : vbcv;
    we = pbc ? we : tc;
    v = inside ? vi : ve;
    w = inside ? wi : we;
}

// insert the sorted lane pair (dmin contests both slots, dmax only best2)
__device__ __forceinline__ void top2_ins2(
    float dist0, float dist1, int te,
    float& best, int& bidx, float& best2, int& bidx2)
{
    float dmin = fminf(dist0, dist1);
    float dmax = fmaxf(dist0, dist1);
    bool first = dist0 <= dist1;
    int imin = first ? te : te + 1;
    int imax = first ? te + 1 : te;

    bool lt1 = dmin < best;
    bool lt2 = dmin < best2;
    best2 = lt1 ? best : (lt2 ? dmin : best2);
    bidx2 = lt1 ? bidx : (lt2 ? imin : bidx2);
    best  = lt1 ? dmin : best;
    bidx  = lt1 ? imin : bidx;

    bool l3 = dmax < best2;
    best2 = l3 ? dmax : best2;
    bidx2 = l3 ? imax : bidx2;
}

// Evaluate one packed triangle-pair against one point (R11 sat-clamp body,
// APP-free selection; emitted DIST pipeline bitwise == proven R7/R11).
__device__ __forceinline__ void eval_pair(
    u64 PX, u64 PY, u64 PZ, u64 KN1,
    u64 NAX, u64 NAY, u64 NAZ, u64 ABX, u64 ABY, u64 ABZ,
    u64 ACX, u64 ACY, u64 ACZ, u64 AA, u64 BB, u64 NGG,
    u64 IA, u64 IB, u64 IC, u64 ID, u64 AMG, u64 CB2, u64 DEN,
    int te, float& best, int& bidx, float& best2, int& bidx2)
{
    u64 APX = f2add(PX, NAX);
    u64 APY = f2add(PY, NAY);
    u64 APZ = f2add(PZ, NAZ);

    u64 D1  = f2fma(ABX, APX, f2fma(ABY, APY, f2mul(ABZ, APZ)));
    u64 D2  = f2fma(ACX, APX, f2fma(ACY, APY, f2mul(ACZ, APZ)));

    u64 VC  = f2fma(AA, D2, f2mul(NGG, D1));
    u64 VB  = f2fma(BB, D1, f2mul(NGG, D2));
    u64 VBC = f2add(VB, VC);

    u64 E1 = f2add(f2fma(KN1, D1, D2), AMG);

    float d1l0, d1l1, d2l0, d2l1, e1l0, e1l1;
    f2unpack(D1, d1l0, d1l1);
    f2unpack(D2, d2l0, d2l1);
    f2unpack(E1, e1l0, e1l1);
    float ia0, ia1, ib0, ib1, ic0, ic1;
    f2unpack(IA, ia0, ia1);
    f2unpack(IB, ib0, ib1);
    f2unpack(IC, ic0, ic1);
    float ta0 = fmul_sat(d1l0, ia0), ta1 = fmul_sat(d1l1, ia1);
    float tb0 = fmul_sat(d2l0, ib0), tb1 = fmul_sat(d2l1, ib1);
    float tc0 = fmul_sat(e1l0, ic0), tc1 = fmul_sat(e1l1, ic1);
    u64 TA = f2pack(ta0, ta1);
    u64 TB = f2pack(tb0, tb1);
    u64 TC = f2pack(tc0, tc1);

    // APP-relative selection distances (common +APP term cancelled)
    u64 D1_2  = f2add(D1, D1);
    u64 ND1_2 = f2mul(D1_2, KN1);
    u64 QAB = f2mul(TA, f2fma(TA, AA, ND1_2));
    u64 ND2_2 = f2mul(f2add(D2, D2), KN1);
    u64 QAC = f2mul(TB, f2fma(TB, BB, ND2_2));
    u64 AMD2 = f2add(AA, ND1_2);                   // aa - 2*d1
    u64 NE1_2 = f2mul(f2add(E1, E1), KN1);
    u64 QBC = f2fma(TC, f2fma(TC, CB2, NE1_2), AMD2);

    u64 VI = f2mul(VB, ID);
    u64 WI = f2mul(VC, ID);

    float vb0, vb1, vc0, vc1, vbc0, vbc1, den0, den1;
    float qab0, qab1, qac0, qac1, qbc0, qbc1, vi0, vi1, wi0, wi1;
    f2unpack(VB, vb0, vb1);    f2unpack(VC, vc0, vc1);
    f2unpack(VBC, vbc0, vbc1); f2unpack(DEN, den0, den1);
    f2unpack(QAB, qab0, qab1); f2unpack(QAC, qac0, qac1);
    f2unpack(QBC, qbc0, qbc1);
    f2unpack(VI, vi0, vi1);    f2unpack(WI, wi0, wi1);

    float v0, w0, v1, w1;
    lane_sel(vb0, vc0, vbc0, den0, qab0, qac0, qbc0, ta0, tb0, tc0, vi0, wi0, v0, w0);
    lane_sel(vb1, vc1, vbc1, den1, qab1, qac1, qbc1, ta1, tb1, tc1, vi1, wi1, v1, w1);

    u64 NV = f2mul(f2pack(v0, v1), KN1);
    u64 NW = f2mul(f2pack(w0, w1), KN1);

    u64 DX = f2fma(NV, ABX, f2fma(NW, ACX, APX));
    u64 DY = f2fma(NV, ABY, f2fma(NW, ACY, APY));
    u64 DZ = f2fma(NV, ABZ, f2fma(NW, ACZ, APZ));
    u64 DIST = f2fma(DX, DX, f2fma(DY, DY, f2mul(DZ, DZ)));
    float dist0, dist1;
    f2unpack(DIST, dist0, dist1);

    top2_ins2(dist0, dist1, te, best, bidx, best2, bidx2);
}

// ---------------------------------------------------------------------------
// Kernel 1: brute-force scan; 2 points per thread share each loaded triangle
// pair (R12-proven balance of amortization vs registers). Top-2 per
// (point, split); f64 arbitration downstream.
// ---------------------------------------------------------------------------
__global__ void __launch_bounds__(BLOCK, 4) k_main(const float* __restrict__ points) {
    __shared__ ulonglong2 sh[TILE_PAIRS * 10];
    int b = blockIdx.z;
    int q0 = blockIdx.x * (BLOCK * PTS_PER_THREAD) + threadIdx.x;
    int q1 = q0 + BLOCK;
    const float* pp0 = points + (size_t)(b * NQ + q0) * 3;
    const float* pp1 = points + (size_t)(b * NQ + q1) * 3;
    u64 PX0 = f2pack(pp0[0], pp0[0]), PY0 = f2pack(pp0[1], pp0[1]), PZ0 = f2pack(pp0[2], pp0[2]);
    u64 PX1 = f2pack(pp1[0], pp1[0]), PY1 = f2pack(pp1[1], pp1[1]), PZ1 = f2pack(pp1[2], pp1[2]);
    const u64 KN1 = f2pack(-1.0f, -1.0f);
    int pairBase = blockIdx.y * PAIRS_PER_SPLIT;

    float bestA  = 3.402823e38f;  int bidxA  = pairBase * 2;
    float bestA2 = 3.402823e38f;  int bidxA2 = pairBase * 2;
    float bestB  = 3.402823e38f;  int bidxB  = pairBase * 2;
    float bestB2 = 3.402823e38f;  int bidxB2 = pairBase * 2;

    for (int tp0 = 0; tp0 < PAIRS_PER_SPLIT; tp0 += TILE_PAIRS) {
        __syncthreads();
        {
            const float4* src = g_tc2 + (size_t)(b * (NF/2) + pairBase + tp0) * 10;
            float4* dst = (float4*)sh;
            for (int i = threadIdx.x; i < TILE_PAIRS * 10; i += BLOCK) dst[i] = src[i];
        }
        __syncthreads();

        #pragma unroll 2
        for (int j = 0; j < TILE_PAIRS; j++) {
            const ulonglong2* tp = sh + j * 10;
            ulonglong2 s0 = tp[0], s1 = tp[1], s2 = tp[2], s3 = tp[3], s4 = tp[4];
            ulonglong2 s5 = tp[5], s6 = tp[6], s7 = tp[7], s8 = tp[8], s9 = tp[9];
            u64 NAX = s0.x, NAY = s0.y, NAZ = s1.x, ABX = s1.y;
            u64 ABY = s2.x, ABZ = s2.y, ACX = s3.x, ACY = s3.y;
            u64 ACZ = s4.x, AA  = s4.y, BB  = s5.x, NGG = s5.y;
            u64 IA  = s6.x, IB  = s6.y, IC  = s7.x, ID  = s7.y;
            u64 AMG = s8.x, CB2 = s8.y, DEN = s9.x;

            int te = (pairBase + tp0 + j) * 2;
            eval_pair(PX0, PY0, PZ0, KN1,
                      NAX, NAY, NAZ, ABX, ABY, ABZ, ACX, ACY, ACZ, AA, BB, NGG,
                      IA, IB, IC, ID, AMG, CB2, DEN,
                      te, bestA, bidxA, bestA2, bidxA2);
            eval_pair(PX1, PY1, PZ1, KN1,
                      NAX, NAY, NAZ, ABX, ABY, ABZ, ACX, ACY, ACZ, AA, BB, NGG,
                      IA, IB, IC, ID, AMG, CB2, DEN,
                      te, bestB, bidxB, bestB2, bidxB2);
        }
    }

    g_cand[(size_t)(b * NQ + q0) * SPLITS + blockIdx.y] =
        make_uint2((unsigned)bidxA, (unsigned)bidxA2);
    g_cand[(size_t)(b * NQ + q1) * SPLITS + blockIdx.y] =
        make_uint2((unsigned)bidxB, (unsigned)bidxB2);
}

// ---------------------------------------------------------------------------
// Reference formula in DOUBLE precision (true-math ordering for arbitration).
// ---------------------------------------------------------------------------
__device__ void ref_eval_d(const float* __restrict__ tp,
                           double px, double py, double pz,
                           double& d2out, double& rxo, double& ryo, double& rzo) {
    double ax = tp[0], ay = tp[1], az = tp[2];
    double bx = tp[3], by = tp[4], bz = tp[5];
    double cx = tp[6], cy = tp[7], cz = tp[8];

    double abx = bx - ax, aby = by - ay, abz = bz - az;
    double acx = cx - ax, acy = cy - ay, acz = cz - az;
    double apx = px - ax, apy = py - ay, apz = pz - az;
    double d1 = abx*apx + aby*apy + abz*apz;
    double d2 = acx*apx + acy*apy + acz*apz;
    double bpx = px - bx, bpy = py - by, bpz = pz - bz;
    double d3 = abx*bpx + aby*bpy + abz*bpz;
    double d4 = acx*bpx + acy*bpy + acz*bpz;
    double cpx = px - cx, cpy = py - cy, cpz = pz - cz;
    double d5 = abx*cpx + aby*cpy + abz*cpz;
    double d6 = acx*cpx + acy*cpy + acz*cpz;

    double vc = d1*d4 - d3*d2;
    double vb = d5*d2 - d1*d6;
    double va = d3*d6 - d5*d4;
    double v_ab = dclamp01(dsafe_div(d1, d1 - d3));
    double w_ac = dclamp01(dsafe_div(d2, d2 - d6));
    double w_bc = dclamp01(dsafe_div(d4 - d3, (d4 - d3) + (d5 - d6)));
    double denom = va + vb + vc;
    double v = dsafe_div(vb, denom);
    double w = dsafe_div(vc, denom);

    double rx = ax + abx*v + acx*w;
    double ry = ay + aby*v + acy*w;
    double rz = az + abz*v + acz*w;

    bool m_bc = (va <= 0.0) && ((d4 - d3) >= 0.0) && ((d5 - d6) >= 0.0);
    if (m_bc) { rx = bx + w_bc*(cx - bx); ry = by + w_bc*(cy - by); rz = bz + w_bc*(cz - bz); }
    bool m_ac = (vb <= 0.0) && (d2 >= 0.0) && (d6 <= 0.0);
    if (m_ac) { rx = ax + w_ac*acx; ry = ay + w_ac*acy; rz = az + w_ac*acz; }
    bool m_ab = (vc <= 0.0) && (d1 >= 0.0) && (d3 <= 0.0);
    if (m_ab) { rx = ax + v_ab*abx; ry = ay + v_ab*aby; rz = az + v_ab*abz; }
    bool m_c = (d6 >= 0.0) && (d5 <= d6);
    if (m_c) { rx = cx; ry = cy; rz = cz; }
    bool m_b = (d3 >= 0.0) && (d4 <= d3);
    if (m_b) { rx = bx; ry = by; rz = bz; }
    bool m_a = (d1 <= 0.0) && (d2 <= 0.0);
    if (m_a) { rx = ax; ry = ay; rz = az; }

    double dxx = px - rx, dyy = py - ry, dzz = pz - rz;
    d2out = dxx*dxx + dyy*dyy + dzz*dzz;
    rxo = rx; ryo = ry; rzo = rz;
}

// ---------------------------------------------------------------------------
// Kernel 2: PARALLEL arbitration — 4 threads per point, each f64-evaluates 4
// of the 16 candidates; butterfly-reduce (bestD, bestI) with idx tie-break;
// sub-lane 0 recomputes the winner's closest point and writes outputs.
// ---------------------------------------------------------------------------
__global__ void k_fin(const float* __restrict__ tris,
                      const float* __restrict__ points,
                      float* __restrict__ out) {
    int gid = blockIdx.x * blockDim.x + threadIdx.x;
    int i = gid >> 2;         // point index
    int sub = gid & 3;        // quarter (splits 2*sub, 2*sub+1)
    if (i >= NPTS) return;
    int b = i / NQ;

    const float* pp = points + (size_t)i * 3;
    double px = pp[0], py = pp[1], pz = pp[2];

    double bestD = 1e300;
    int bestI = 0x7FFFFFFF;

    #pragma unroll
    for (int s = sub * 2; s < sub * 2 + 2; s++) {
        uint2 c = g_cand[(size_t)i * SPLITS + s];
        #pragma unroll
        for (int k = 0; k < 2; k++) {
            int idx = (k == 0) ? (int)c.x : (int)c.y;
            const float* tp = tris + (size_t)(b * NF + idx) * 9;
            double d2, rx, ry, rz;
            ref_eval_d(tp, px, py, pz, d2, rx, ry, rz);
            bool take = (d2 < bestD) || (d2 == bestD && idx < bestI);
            if (take) { bestD = d2; bestI = idx; }
        }
    }

    // butterfly reduce over the 4 sub-lanes (same warp: gid consecutive)
    #pragma unroll
    for (int off = 1; off < 4; off <<= 1) {
        double oD = __shfl_xor_sync(0xFFFFFFFFu, bestD, off);
        int    oI = __shfl_xor_sync(0xFFFFFFFFu, bestI, off);
        if (oD < bestD || (oD == bestD && oI < bestI)) { bestD = oD; bestI = oI; }
    }

    if (sub == 0) {
        const float* tp = tris + (size_t)(b * NF + bestI) * 9;
        double d2, rx, ry, rz;
        ref_eval_d(tp, px, py, pz, d2, rx, ry, rz);
        out[i] = (float)d2;                                  // distances [2,16384]
        out[NPTS + (size_t)i*3 + 0] = (float)rx;             // closest_points
        out[NPTS + (size_t)i*3 + 1] = (float)ry;
        out[NPTS + (size_t)i*3 + 2] = (float)rz;
        out[(size_t)NPTS*4 + i] = (float)bestI;              // closest_faces
    }
}

extern "C" void kernel_launch(void* const* d_in, const int* in_sizes, int n_in,
                              void* d_out, int out_size) {
    const float* tris = (const float*)d_in[0];   // [2,4096,3,3]
    const float* pts  = (const float*)d_in[1];   // [2,16384,3]
    float* out = (float*)d_out;

    k_pre<<<(NB*NF + 255) / 256, 256>>>(tris);
    dim3 grid(NQ / (BLOCK * PTS_PER_THREAD), SPLITS, NB);
    k_main<<<grid, BLOCK>>>(pts);
    k_fin<<<(NPTS * 4 + 255) / 256, 256>>>(tris, pts, out);
}